// round 1
// baseline (speedup 1.0000x reference)
#include <cuda_runtime.h>

// Problem constants (shapes fixed by the dataset)
#define T_IN     60          // input-driven timesteps
#define CH       128         // input channels
#define NPIX     4096        // batch rows (pixel samples)
#define HID      128         // hidden size
#define G4       512         // 4*HID gate width
#define RBLK     32          // rows per CTA
#define NCTA     (NPIX / RBLK)  // 128 CTAs
#define NTHREADS 256
#define KT       32          // K tile

// Scratch weights (prepared once per launch). ~770 KB device globals (allowed).
__device__ float g_WtCat[256 * G4];  // [k][g]: k<128 -> W_hh[g][k], k>=128 -> W_ih[g][k-128]
__device__ float g_WsumT[128 * G4];  // [k][g]: W_ih[g][k] + W_hh[g][k]  (AR phase)
__device__ float g_bias[G4];         // b_ih + b_hh

__global__ void prep_kernel(const float* __restrict__ W_ih, const float* __restrict__ W_hh,
                            const float* __restrict__ b_ih, const float* __restrict__ b_hh) {
    int idx = blockIdx.x * blockDim.x + threadIdx.x;
    if (idx < 128 * G4) {
        int k = idx >> 9;       // / 512
        int g = idx & 511;
        float wih = W_ih[g * CH + k];
        float whh = W_hh[g * HID + k];
        g_WtCat[k * G4 + g]         = whh;
        g_WtCat[(128 + k) * G4 + g] = wih;
        g_WsumT[k * G4 + g]         = wih + whh;
    }
    if (idx < G4) g_bias[idx] = b_ih[idx] + b_hh[idx];
}

__device__ __forceinline__ float sigm(float x) {
    return __fdividef(1.0f, 1.0f + __expf(-x));
}
__device__ __forceinline__ float tanh_f(float x) {
    // 2*sigmoid(2x)-1 : cancellation-safe for our gate range, MUFU.EX2-based
    return 2.0f * __fdividef(1.0f, 1.0f + __expf(-2.0f * x)) - 1.0f;
}

// Dynamic smem layout (floats):
//   [0,     4096)  sh_h  [32][128]
//   [4096,  8192)  sh_c  [32][128]
//   [8192, 12320)  sh_x  [32][129]  (padded: conflict-free STS of x tile)
//   [12320,28704)  sh_bg [32][512]  (B K-tile, reused as gates buffer)
#define SMEM_FLOATS 28704
#define SMEM_BYTES  (SMEM_FLOATS * 4)

extern __shared__ float smem[];

__global__ __launch_bounds__(NTHREADS, 1)
void lstm_persist_kernel(const float* __restrict__ image, float* __restrict__ out, int total_t) {
    float* sh_h  = smem;
    float* sh_c  = smem + 4096;
    float* sh_x  = smem + 8192;
    float* sh_bg = smem + 12320;

    const int tid = threadIdx.x;
    const int ty  = tid >> 5;   // 0..7  -> row group (4 rows)
    const int tx  = tid & 31;   // 0..31 -> col lane (cols tx + 32*jj)
    const int row_base = blockIdx.x * RBLK;

    // h = c = 0
    for (int i = tid; i < RBLK * HID; i += NTHREADS) { sh_h[i] = 0.0f; sh_c[i] = 0.0f; }

    for (int t = 0; t < total_t; ++t) {
        const bool ph1 = (t < T_IN);
        const float* __restrict__ Bmat = ph1 ? g_WtCat : g_WsumT;
        const int Ktot = ph1 ? 256 : 128;

        if (ph1) {
            // stage x_t tile: sh_x[r][c] = image[t][c][row_base + r]   (coalesced over r)
            for (int i = tid; i < RBLK * CH; i += NTHREADS) {
                int cc = i >> 5;
                int rr = i & 31;
                sh_x[rr * (CH + 1) + cc] =
                    image[((size_t)t * CH + cc) * (size_t)NPIX + row_base + rr];
            }
        }

        // accumulators init with fused bias
        float acc[4][16];
        #pragma unroll
        for (int jj = 0; jj < 16; ++jj) {
            float bv = g_bias[tx + 32 * jj];
            #pragma unroll
            for (int i = 0; i < 4; ++i) acc[i][jj] = bv;
        }

        for (int kt = 0; kt < Ktot; kt += KT) {
            __syncthreads();  // prev tile (or prev-step gates / h) fully consumed
            // stage B K-tile [KT][512] (L2-resident weights)
            {
                const float4* src = (const float4*)(Bmat + (size_t)kt * G4);
                float4* dst = (float4*)sh_bg;
                for (int i = tid; i < KT * G4 / 4; i += NTHREADS) dst[i] = src[i];
            }
            __syncthreads();

            const float* Abase;
            int Astride;
            if (kt < 128) { Abase = sh_h + (ty * 4) * HID + kt;          Astride = HID; }
            else          { Abase = sh_x + (ty * 4) * (CH + 1) + (kt - 128); Astride = CH + 1; }

            #pragma unroll
            for (int kk = 0; kk < KT; ++kk) {
                float a0 = Abase[0 * Astride + kk];   // warp-broadcast LDS
                float a1 = Abase[1 * Astride + kk];
                float a2 = Abase[2 * Astride + kk];
                float a3 = Abase[3 * Astride + kk];
                const float* brow = sh_bg + kk * G4 + tx;  // bank tx: conflict-free
                #pragma unroll
                for (int jj = 0; jj < 16; ++jj) {
                    float bv = brow[32 * jj];
                    acc[0][jj] += a0 * bv;
                    acc[1][jj] += a1 * bv;
                    acc[2][jj] += a2 * bv;
                    acc[3][jj] += a3 * bv;
                }
            }
        }

        __syncthreads();  // all B reads done -> reuse sh_bg for gates
        #pragma unroll
        for (int i = 0; i < 4; ++i) {
            int r = ty * 4 + i;
            #pragma unroll
            for (int jj = 0; jj < 16; ++jj)
                sh_bg[r * G4 + tx + 32 * jj] = acc[i][jj];
        }
        __syncthreads();

        // epilogue: activations + state update + output write
        #pragma unroll
        for (int i = 0; i < 4; ++i) {
            int r = ty * 4 + i;
            #pragma unroll
            for (int jj = 0; jj < 4; ++jj) {
                int j = tx + 32 * jj;
                float gi = sigm  (sh_bg[r * G4 +           j]);
                float gf = sigm  (sh_bg[r * G4 +     HID + j]);
                float gg = tanh_f(sh_bg[r * G4 + 2 * HID + j]);
                float go = sigm  (sh_bg[r * G4 + 3 * HID + j]);
                float cn = gf * sh_c[r * HID + j] + gi * gg;
                sh_c[r * HID + j] = cn;
                float hn = go * tanh_f(cn);
                sh_h[r * HID + j] = hn;
                out[((size_t)(row_base + r) * total_t + t) * HID + j] = hn;
            }
        }
        // next iteration's first __syncthreads orders sh_h/sh_bg reuse
    }
}

extern "C" void kernel_launch(void* const* d_in, const int* in_sizes, int n_in,
                              void* d_out, int out_size) {
    const float* image = (const float*)d_in[0];
    // d_in[1] = mask (unused by reference forward)
    const float* W_ih  = (const float*)d_in[2];
    const float* W_hh  = (const float*)d_in[3];
    const float* b_ih  = (const float*)d_in[4];
    const float* b_hh  = (const float*)d_in[5];
    // d_in[6] = gp_affected_timesteps; total_t derived from out_size instead
    float* out = (float*)d_out;

    int total_t = out_size / (NPIX * HID);   // = T + (T - gp - 1) = 114

    prep_kernel<<<(128 * G4 + NTHREADS - 1) / NTHREADS, NTHREADS>>>(W_ih, W_hh, b_ih, b_hh);

    cudaFuncSetAttribute(lstm_persist_kernel,
                         cudaFuncAttributeMaxDynamicSharedMemorySize, SMEM_BYTES);
    lstm_persist_kernel<<<NCTA, NTHREADS, SMEM_BYTES>>>(image, out, total_t);
}